// round 3
// baseline (speedup 1.0000x reference)
#include <cuda_runtime.h>
#include <cstdint>
#include <cstddef>

#define BATCH 4096
#define DIM   1024
#define TDICT 32768
#define TOPK  64

// ---------------- scratch (device globals: no runtime allocation allowed) ---
__device__ float g_xc[(size_t)BATCH * DIM];          // centered input, 16 MB
__device__ float g_acts[(size_t)BATCH * TDICT];      // relu(pre_acts), 512 MB
__device__ int   g_tidx[BATCH * TOPK];
__device__ float g_tval[BATCH * TOPK];

// ---------------- kernel 1: xc = x - b_dec ---------------------------------
__global__ void center_kernel(const float* __restrict__ x,
                              const float* __restrict__ b_dec) {
    int i = blockIdx.x * blockDim.x + threadIdx.x;   // over BATCH*DIM/4 float4
    float4 xv = reinterpret_cast<const float4*>(x)[i];
    float4 bv = reinterpret_cast<const float4*>(b_dec)[i & (DIM / 4 - 1)];
    xv.x -= bv.x; xv.y -= bv.y; xv.z -= bv.z; xv.w -= bv.w;
    reinterpret_cast<float4*>(g_xc)[i] = xv;
}

// ---------------- kernel 2: acts = relu(xc @ W_enc + b_enc) -----------------
// fp32 SGEMM, BM=BN=128, BK=16, 256 threads, 8x8 micro-tile per thread.
#define BM 128
#define BN 128
#define BK 16

__global__ __launch_bounds__(256, 1)
void sgemm_relu_kernel(const float* __restrict__ W, const float* __restrict__ bias) {
    __shared__ float As[BK][BM];
    __shared__ float Bs[BK][BN];

    const int tid = threadIdx.x;
    const int tx = tid & 15;          // 0..15 -> N
    const int ty = tid >> 4;          // 0..15 -> M
    const int m0 = blockIdx.y * BM;
    const int n0 = blockIdx.x * BN;

    // A-tile load map: 128 rows x 16 cols; thread -> (row=tid/2, col8=(tid&1)*8)
    const int ar = tid >> 1;
    const int ac = (tid & 1) * 8;
    // B-tile load map: 16 rows x 128 cols; thread -> (row=tid/16, col8=(tid&15)*8)
    const int br = tid >> 4;
    const int bc = (tid & 15) * 8;

    float acc[8][8];
#pragma unroll
    for (int i = 0; i < 8; i++)
#pragma unroll
        for (int j = 0; j < 8; j++) acc[i][j] = 0.f;

    const float* Ag = g_xc + (size_t)(m0 + ar) * DIM + ac;
    const float* Bg = W + (size_t)br * TDICT + n0 + bc;

    for (int k0 = 0; k0 < DIM; k0 += BK) {
        float4 a0 = *reinterpret_cast<const float4*>(Ag + k0);
        float4 a1 = *reinterpret_cast<const float4*>(Ag + k0 + 4);
        As[ac + 0][ar] = a0.x; As[ac + 1][ar] = a0.y;
        As[ac + 2][ar] = a0.z; As[ac + 3][ar] = a0.w;
        As[ac + 4][ar] = a1.x; As[ac + 5][ar] = a1.y;
        As[ac + 6][ar] = a1.z; As[ac + 7][ar] = a1.w;
        const float* bptr = Bg + (size_t)k0 * TDICT;
        *reinterpret_cast<float4*>(&Bs[br][bc])     = *reinterpret_cast<const float4*>(bptr);
        *reinterpret_cast<float4*>(&Bs[br][bc + 4]) = *reinterpret_cast<const float4*>(bptr + 4);
        __syncthreads();

#pragma unroll
        for (int kk = 0; kk < BK; kk++) {
            float a[8], b[8];
            *reinterpret_cast<float4*>(a)     = *reinterpret_cast<float4*>(&As[kk][ty * 8]);
            *reinterpret_cast<float4*>(a + 4) = *reinterpret_cast<float4*>(&As[kk][ty * 8 + 4]);
            *reinterpret_cast<float4*>(b)     = *reinterpret_cast<float4*>(&Bs[kk][tx * 8]);
            *reinterpret_cast<float4*>(b + 4) = *reinterpret_cast<float4*>(&Bs[kk][tx * 8 + 4]);
#pragma unroll
            for (int i = 0; i < 8; i++)
#pragma unroll
                for (int j = 0; j < 8; j++) acc[i][j] += a[i] * b[j];
        }
        __syncthreads();
    }

    float bv[8];
#pragma unroll
    for (int j = 0; j < 8; j++) bv[j] = bias[n0 + tx * 8 + j];

#pragma unroll
    for (int i = 0; i < 8; i++) {
        float* crow = g_acts + (size_t)(m0 + ty * 8 + i) * TDICT + n0 + tx * 8;
        float4 o0, o1;
        float v;
        v = acc[i][0] + bv[0]; o0.x = v > 0.f ? v : 0.f;
        v = acc[i][1] + bv[1]; o0.y = v > 0.f ? v : 0.f;
        v = acc[i][2] + bv[2]; o0.z = v > 0.f ? v : 0.f;
        v = acc[i][3] + bv[3]; o0.w = v > 0.f ? v : 0.f;
        v = acc[i][4] + bv[4]; o1.x = v > 0.f ? v : 0.f;
        v = acc[i][5] + bv[5]; o1.y = v > 0.f ? v : 0.f;
        v = acc[i][6] + bv[6]; o1.z = v > 0.f ? v : 0.f;
        v = acc[i][7] + bv[7]; o1.w = v > 0.f ? v : 0.f;
        *reinterpret_cast<float4*>(crow)     = o0;
        *reinterpret_cast<float4*>(crow + 4) = o1;
    }
}

// ---------------- kernel 3: per-row top-64 (radix select in SMEM) -----------
// Values are post-ReLU (>=0), so uint bit pattern order == float order.
// Tie-break matches jax.lax.top_k: strictly-greater taken, then lowest-index
// ties at the threshold value.
__global__ __launch_bounds__(256, 1)
void topk_kernel() {
    extern __shared__ unsigned int sv[];            // TDICT uints (128 KB)
    __shared__ unsigned int hist[256];
    __shared__ unsigned int sW1[8], sW2[8];
    __shared__ unsigned int s_pref, s_kneed;
    __shared__ int s_cgt, s_ceq;

    const int tid = threadIdx.x;
    const int row = blockIdx.x;
    const unsigned int* arow =
        reinterpret_cast<const unsigned int*>(g_acts + (size_t)row * TDICT);
    for (int i = tid; i < TDICT; i += 256) sv[i] = arow[i];

    unsigned int pref = 0, kneed = TOPK;
    for (int p = 24; p >= 0; p -= 8) {
        __syncthreads();
        hist[tid] = 0;
        __syncthreads();
        const unsigned int maskH = (p == 24) ? 0u : (0xFFFFFFFFu << (p + 8));
        for (int i = tid; i < TDICT; i += 256) {
            unsigned int v = sv[i];
            if ((v & maskH) == pref) atomicAdd(&hist[(v >> p) & 0xFFu], 1u);
        }
        __syncthreads();
        if (tid == 0) {
            unsigned int cum = 0;
            int b = 255;
            for (; b > 0; b--) {
                if (cum + hist[b] >= kneed) break;
                cum += hist[b];
            }
            s_pref = pref | ((unsigned int)b << p);
            s_kneed = kneed - cum;
        }
        __syncthreads();
        pref = s_pref;
        kneed = s_kneed;
    }

    const unsigned int thr = pref;       // bits of the 64th-largest value
    const int needeq = (int)kneed;       // how many ==thr to take
    const int ngt = TOPK - needeq;       // count of strictly-greater

    if (tid == 0) { s_cgt = 0; s_ceq = 0; }
    __syncthreads();

    const int lane = tid & 31, wid = tid >> 5;
    int*   oidx = g_tidx + row * TOPK;
    float* oval = g_tval + row * TOPK;

    for (int c0 = 0; c0 < TDICT; c0 += 256) {
        const unsigned int v = sv[c0 + tid];
        const bool pgt = v > thr;
        const bool peq = (v == thr);
        const unsigned int b1 = __ballot_sync(0xffffffffu, pgt);
        const unsigned int b2 = __ballot_sync(0xffffffffu, peq);
        if (lane == 0) { sW1[wid] = __popc(b1); sW2[wid] = __popc(b2); }
        __syncthreads();
        int off1 = 0, off2 = 0, t1 = 0, t2 = 0;
#pragma unroll
        for (int w = 0; w < 8; w++) {
            if (w < wid) { off1 += (int)sW1[w]; off2 += (int)sW2[w]; }
            t1 += (int)sW1[w]; t2 += (int)sW2[w];
        }
        const int base1 = s_cgt, base2 = s_ceq;
        const unsigned int lmask = (1u << lane) - 1u;
        const int r1 = base1 + off1 + __popc(b1 & lmask);
        const int r2 = base2 + off2 + __popc(b2 & lmask);
        if (pgt)               { oidx[r1] = c0 + tid;       oval[r1] = __uint_as_float(v); }
        if (peq && r2 < needeq){ oidx[ngt + r2] = c0 + tid; oval[ngt + r2] = __uint_as_float(v); }
        __syncthreads();
        if (tid == 0) { s_cgt = base1 + t1; s_ceq = base2 + t2; }
        __syncthreads();
        if (s_cgt >= ngt && s_ceq >= needeq) break;
    }
}

// ---------------- kernel 4: nested group decode -----------------------------
__global__ __launch_bounds__(256, 1)
void decode_kernel(const float* __restrict__ Wd, const float* __restrict__ bdec,
                   float* __restrict__ out) {
    __shared__ int   sidx[TOPK];
    __shared__ float sval[TOPK];
    const int row = blockIdx.x, tid = threadIdx.x;
    if (tid < TOPK) {
        sidx[tid] = g_tidx[row * TOPK + tid];
        sval[tid] = g_tval[row * TOPK + tid];
    }
    __syncthreads();

    float acc[4];
#pragma unroll
    for (int j = 0; j < 4; j++) acc[j] = bdec[tid + j * 256];

    const int bounds[4] = {0, 2048, 8192, TDICT};
#pragma unroll
    for (int g = 0; g < 3; g++) {
        for (int t = 0; t < TOPK; t++) {
            const int idx = sidx[t];
            if (idx >= bounds[g] && idx < bounds[g + 1]) {
                const float v = sval[t];
                const float* w = Wd + (size_t)idx * DIM;
#pragma unroll
                for (int j = 0; j < 4; j++) acc[j] += v * w[tid + j * 256];
            }
        }
        const size_t o = ((size_t)g * BATCH + row) * DIM;
#pragma unroll
        for (int j = 0; j < 4; j++) out[o + tid + j * 256] = acc[j];
    }
}

// ---------------- launch ----------------------------------------------------
extern "C" void kernel_launch(void* const* d_in, const int* in_sizes, int n_in,
                              void* d_out, int out_size) {
    const float* x     = (const float*)d_in[0];
    const float* W_enc = (const float*)d_in[1];
    const float* b_enc = (const float*)d_in[2];
    const float* W_dec = (const float*)d_in[3];
    const float* b_dec = (const float*)d_in[4];
    float* out = (float*)d_out;

    cudaFuncSetAttribute(topk_kernel,
                         cudaFuncAttributeMaxDynamicSharedMemorySize,
                         TDICT * (int)sizeof(unsigned int));

    center_kernel<<<(BATCH * DIM / 4) / 256, 256>>>(x, b_dec);

    dim3 grid(TDICT / BN, BATCH / BM);
    sgemm_relu_kernel<<<grid, 256>>>(W_enc, b_enc);

    topk_kernel<<<BATCH, 256, TDICT * sizeof(unsigned int)>>>();

    decode_kernel<<<BATCH, 256>>>(W_dec, b_dec, out);
}

// round 7
// speedup vs baseline: 4.8689x; 4.8689x over previous
#include <cuda_runtime.h>
#include <cuda_bf16.h>
#include <cstdint>
#include <cstddef>

#define BATCH 4096
#define DIM   1024
#define TDICT 32768
#define TOPK  64
#define CAND_MAX 512

// ---------------- scratch (device globals) ----------------------------------
__device__ __nv_bfloat16 g_actsb[(size_t)BATCH * TDICT];   // approx acts, 256 MB
__device__ float         g_xc[(size_t)BATCH * DIM];        // centered x fp32, 16 MB
__device__ __nv_bfloat16 g_xb[(size_t)BATCH * DIM];        // centered x bf16, 8 MB
__device__ float         g_Wt[(size_t)TDICT * DIM];        // W^T fp32, 128 MB
__device__ __nv_bfloat16 g_Wb[(size_t)TDICT * DIM];        // W^T bf16, 64 MB
__device__ int   g_cand[(size_t)BATCH * CAND_MAX];         // 8 MB
__device__ int   g_ccnt[BATCH];
__device__ int   g_tidx[BATCH * TOPK];
__device__ float g_tval[BATCH * TOPK];

// ---------------- helpers ---------------------------------------------------
__device__ __forceinline__ uint32_t smem_u32(const void* p) {
    uint32_t a;
    asm("{ .reg .u64 t; cvta.to.shared.u64 t, %1; cvt.u32.u64 %0, t; }" : "=r"(a) : "l"(p));
    return a;
}
__device__ __forceinline__ void cp16(uint32_t dst, const void* src) {
    asm volatile("cp.async.cg.shared.global [%0], [%1], 16;" :: "r"(dst), "l"(src));
}
__device__ __forceinline__ void ldsm4(uint32_t& r0, uint32_t& r1, uint32_t& r2,
                                      uint32_t& r3, uint32_t addr) {
    asm volatile("ldmatrix.sync.aligned.m8n8.x4.shared.b16 {%0,%1,%2,%3}, [%4];"
                 : "=r"(r0), "=r"(r1), "=r"(r2), "=r"(r3) : "r"(addr));
}
__device__ __forceinline__ void mma16816(float* c, const uint32_t* a,
                                         const uint32_t* b) {
    asm volatile(
        "mma.sync.aligned.m16n8k16.row.col.f32.bf16.bf16.f32 "
        "{%0,%1,%2,%3}, {%4,%5,%6,%7}, {%8,%9}, {%0,%1,%2,%3};"
        : "+f"(c[0]), "+f"(c[1]), "+f"(c[2]), "+f"(c[3])
        : "r"(a[0]), "r"(a[1]), "r"(a[2]), "r"(a[3]), "r"(b[0]), "r"(b[1]));
}

// ---------------- kernel 1: center x -> fp32 + bf16 -------------------------
__global__ void split_x_kernel(const float* __restrict__ x,
                               const float* __restrict__ b_dec) {
    int i = blockIdx.x * 256 + threadIdx.x;
    float v = x[i] - b_dec[i & (DIM - 1)];
    g_xc[i] = v;
    g_xb[i] = __float2bfloat16_rn(v);
}

// ---------------- kernel 2: transpose W_enc -> fp32 + bf16 ------------------
__global__ __launch_bounds__(256, 4)
void split_w_kernel(const float* __restrict__ W) {
    __shared__ float tile[32][33];
    const int n0 = blockIdx.x * 32, k0 = blockIdx.y * 32;
    const int tx = threadIdx.x & 31, ty = threadIdx.x >> 5;
#pragma unroll
    for (int i = 0; i < 4; i++)
        tile[ty + 8 * i][tx] = W[(size_t)(k0 + ty + 8 * i) * TDICT + n0 + tx];
    __syncthreads();
    const int r = threadIdx.x >> 3, c0 = (threadIdx.x & 7) * 4;
#pragma unroll
    for (int i = 0; i < 4; i++) {
        float v = tile[c0 + i][r];
        size_t o = (size_t)(n0 + r) * DIM + k0 + c0 + i;
        g_Wt[o] = v;
        g_Wb[o] = __float2bfloat16_rn(v);
    }
}

// ---------------- kernel 3: bf16 HMMA GEMM + bias + relu -> bf16 acts -------
// C[128,128] per CTA, BK=32, 8 warps (2x4), warp tile 64x32, 2-stage cp.async.
// smem rows padded to 80B so ldmatrix (8 rows x 16B) is bank-conflict-free.
#define AROWB 80
#define TILEB (128 * AROWB)

__global__ __launch_bounds__(256, 2)
void hgemm_kernel(const float* __restrict__ bias) {
    __shared__ __align__(16) uint8_t sA[2][TILEB];
    __shared__ __align__(16) uint8_t sB[2][TILEB];

    const int tid = threadIdx.x, lane = tid & 31, wid = tid >> 5;
    const int m0 = blockIdx.x * 128, n0 = blockIdx.y * 128;
    const int wm = (wid >> 2) * 64, wn = (wid & 3) * 32;

    float c[4][4][4];
#pragma unroll
    for (int i = 0; i < 4; i++)
#pragma unroll
        for (int j = 0; j < 4; j++)
#pragma unroll
            for (int k = 0; k < 4; k++) c[i][j][k] = 0.f;

    const uint32_t uA0 = smem_u32(sA[0]), uB0 = smem_u32(sB[0]);

    // stage loader: 128 rows x 4 chunks(16B) for A and B
    auto load_tile = [&](int buf, int k0) {
        const uint32_t ab = uA0 + buf * TILEB, bb = uB0 + buf * TILEB;
#pragma unroll
        for (int i = 0; i < 2; i++) {
            int id = tid + 256 * i;
            int row = id >> 2, ch = id & 3;
            cp16(ab + row * AROWB + ch * 16,
                 (const char*)(g_xb + (size_t)(m0 + row) * DIM + k0) + ch * 16);
            cp16(bb + row * AROWB + ch * 16,
                 (const char*)(g_Wb + (size_t)(n0 + row) * DIM + k0) + ch * 16);
        }
        asm volatile("cp.async.commit_group;" ::: "memory");
    };

    load_tile(0, 0);

    for (int s = 0; s < DIM / 32; s++) {
        if (s + 1 < DIM / 32) {
            load_tile((s + 1) & 1, (s + 1) * 32);
            asm volatile("cp.async.wait_group 1;" ::: "memory");
        } else {
            asm volatile("cp.async.wait_group 0;" ::: "memory");
        }
        __syncthreads();

        const uint32_t ab = uA0 + (s & 1) * TILEB, bb = uB0 + (s & 1) * TILEB;
#pragma unroll
        for (int ks = 0; ks < 2; ks++) {
            uint32_t a[4][4];
#pragma unroll
            for (int mt = 0; mt < 4; mt++) {
                uint32_t addr = ab + (wm + mt * 16 + (lane & 15)) * AROWB +
                                ks * 32 + ((lane >> 4) << 4);
                ldsm4(a[mt][0], a[mt][1], a[mt][2], a[mt][3], addr);
            }
            uint32_t b[4][2];
#pragma unroll
            for (int nh = 0; nh < 2; nh++) {
                uint32_t addr = bb +
                    (wn + nh * 16 + ((lane & 16) >> 1) + (lane & 7)) * AROWB +
                    ks * 32 + (((lane >> 3) & 1) << 4);
                uint32_t r0, r1, r2, r3;
                ldsm4(r0, r1, r2, r3, addr);
                b[nh * 2 + 0][0] = r0; b[nh * 2 + 0][1] = r1;
                b[nh * 2 + 1][0] = r2; b[nh * 2 + 1][1] = r3;
            }
#pragma unroll
            for (int mt = 0; mt < 4; mt++)
#pragma unroll
                for (int nt = 0; nt < 4; nt++)
                    mma16816(c[mt][nt], a[mt], b[nt]);
        }
        __syncthreads();
    }

    // epilogue: bias + relu -> bf16
#pragma unroll
    for (int mt = 0; mt < 4; mt++) {
        const int row = m0 + wm + mt * 16 + (lane >> 2);
#pragma unroll
        for (int nt = 0; nt < 4; nt++) {
            const int col = n0 + wn + nt * 8 + (lane & 3) * 2;
            const float b0 = bias[col], b1 = bias[col + 1];
            __nv_bfloat162 p0, p1;
            p0.x = __float2bfloat16_rn(fmaxf(c[mt][nt][0] + b0, 0.f));
            p0.y = __float2bfloat16_rn(fmaxf(c[mt][nt][1] + b1, 0.f));
            p1.x = __float2bfloat16_rn(fmaxf(c[mt][nt][2] + b0, 0.f));
            p1.y = __float2bfloat16_rn(fmaxf(c[mt][nt][3] + b1, 0.f));
            *reinterpret_cast<__nv_bfloat162*>(
                g_actsb + (size_t)row * TDICT + col) = p0;
            *reinterpret_cast<__nv_bfloat162*>(
                g_actsb + (size_t)(row + 8) * TDICT + col) = p1;
        }
    }
}

// ---------------- kernel 4: approx 64th value + candidate collection --------
__global__ __launch_bounds__(256, 1)
void topk_approx_kernel() {
    extern __shared__ unsigned short sv[];       // 32768 bf16 bit patterns, 64 KB
    __shared__ unsigned int hist[256];
    __shared__ unsigned int s_b1, s_kneed, s_thr;
    __shared__ int scnt;

    const int tid = threadIdx.x, row = blockIdx.x;
    const uint4* src = reinterpret_cast<const uint4*>(g_actsb + (size_t)row * TDICT);
    for (int i = tid; i < TDICT / 8; i += 256)
        reinterpret_cast<uint4*>(sv)[i] = src[i];

    hist[tid] = 0;
    __syncthreads();
    for (int i = tid; i < TDICT; i += 256)
        atomicAdd(&hist[sv[i] >> 8], 1u);
    __syncthreads();
    if (tid == 0) {
        unsigned int cum = 0; int b = 255;
        for (; b > 0; b--) { if (cum + hist[b] >= TOPK) break; cum += hist[b]; }
        s_b1 = (unsigned)b; s_kneed = TOPK - cum;
    }
    __syncthreads();
    const unsigned int b1 = s_b1, kneed = s_kneed;
    hist[tid] = 0;
    __syncthreads();
    for (int i = tid; i < TDICT; i += 256) {
        unsigned int v = sv[i];
        if ((v >> 8) == b1) atomicAdd(&hist[v & 0xFFu], 1u);
    }
    __syncthreads();
    if (tid == 0) {
        unsigned int cum = 0; int b = 255;
        for (; b > 0; b--) { if (cum + hist[b] >= kneed) break; cum += hist[b]; }
        s_thr = (b1 << 8) | (unsigned)b;
        scnt = 0;
    }
    __syncthreads();

    const float thr_f = __uint_as_float(((unsigned)s_thr) << 16);
    const float cut = fmaxf(thr_f - 0.2f, 0.0f);       // margin >> max approx err
    for (int i = tid; i < TDICT; i += 256) {
        float f = __uint_as_float(((unsigned)sv[i]) << 16);
        if (f > cut) {
            int p = atomicAdd(&scnt, 1);
            if (p < CAND_MAX) g_cand[(size_t)row * CAND_MAX + p] = i;
        }
    }
    __syncthreads();
    if (tid == 0) g_ccnt[row] = scnt < CAND_MAX ? scnt : CAND_MAX;
}

// ---------------- kernel 5: exact fp32 refinement + exact top-64 ------------
__global__ __launch_bounds__(256, 1)
void refine_kernel(const float* __restrict__ bias) {
    __shared__ float xs[DIM];
    __shared__ unsigned long long skey[CAND_MAX];
    __shared__ float svv[CAND_MAX];
    __shared__ int   sidx[CAND_MAX];

    const int row = blockIdx.x, tid = threadIdx.x;
    const int lane = tid & 31, wid = tid >> 5;
    for (int i = tid; i < DIM; i += 256) xs[i] = g_xc[(size_t)row * DIM + i];
    const int cnt = g_ccnt[row];
    __syncthreads();

    for (int c = wid; c < cnt; c += 8) {
        const int idx = g_cand[(size_t)row * CAND_MAX + c];
        const float* w = g_Wt + (size_t)idx * DIM;
        float a0 = 0.f, a1 = 0.f, a2 = 0.f, a3 = 0.f;
#pragma unroll
        for (int j = 0; j < DIM; j += 128) {
            a0 += xs[j + lane]      * __ldg(w + j + lane);
            a1 += xs[j + lane + 32] * __ldg(w + j + lane + 32);
            a2 += xs[j + lane + 64] * __ldg(w + j + lane + 64);
            a3 += xs[j + lane + 96] * __ldg(w + j + lane + 96);
        }
        float acc = (a0 + a1) + (a2 + a3);
#pragma unroll
        for (int o = 16; o > 0; o >>= 1)
            acc += __shfl_xor_sync(0xffffffffu, acc, o);
        if (lane == 0) {
            float v = fmaxf(acc + bias[idx], 0.f);
            skey[c] = ((unsigned long long)__float_as_uint(v) << 32) |
                      (unsigned)(0xFFFFFFFFu - (unsigned)idx);  // lower idx wins ties
            svv[c] = v;
            sidx[c] = idx;
        }
    }
    __syncthreads();

    for (int c = tid; c < cnt; c += 256) {
        const unsigned long long k = skey[c];
        int r = 0;
        for (int j = 0; j < cnt; j++) r += (skey[j] > k);
        if (r < TOPK) {
            g_tidx[row * TOPK + r] = sidx[c];
            g_tval[row * TOPK + r] = svv[c];
        }
    }
}

// ---------------- kernel 6: nested group decode -----------------------------
__global__ __launch_bounds__(256, 1)
void decode_kernel(const float* __restrict__ Wd, const float* __restrict__ bdec,
                   float* __restrict__ out) {
    __shared__ int   sidx[TOPK];
    __shared__ float sval[TOPK];
    const int row = blockIdx.x, tid = threadIdx.x;
    if (tid < TOPK) {
        sidx[tid] = g_tidx[row * TOPK + tid];
        sval[tid] = g_tval[row * TOPK + tid];
    }
    __syncthreads();

    float acc[4];
#pragma unroll
    for (int j = 0; j < 4; j++) acc[j] = bdec[tid + j * 256];

    const int bounds[4] = {0, 2048, 8192, TDICT};
#pragma unroll
    for (int g = 0; g < 3; g++) {
        for (int t = 0; t < TOPK; t++) {
            const int idx = sidx[t];
            if (idx >= bounds[g] && idx < bounds[g + 1]) {
                const float v = sval[t];
                const float* w = Wd + (size_t)idx * DIM;
#pragma unroll
                for (int j = 0; j < 4; j++) acc[j] += v * w[tid + j * 256];
            }
        }
        const size_t o = ((size_t)g * BATCH + row) * DIM;
#pragma unroll
        for (int j = 0; j < 4; j++) out[o + tid + j * 256] = acc[j];
    }
}

// ---------------- launch ----------------------------------------------------
extern "C" void kernel_launch(void* const* d_in, const int* in_sizes, int n_in,
                              void* d_out, int out_size) {
    const float* x     = (const float*)d_in[0];
    const float* W_enc = (const float*)d_in[1];
    const float* b_enc = (const float*)d_in[2];
    const float* W_dec = (const float*)d_in[3];
    const float* b_dec = (const float*)d_in[4];
    float* out = (float*)d_out;

    cudaFuncSetAttribute(topk_approx_kernel,
                         cudaFuncAttributeMaxDynamicSharedMemorySize,
                         TDICT * (int)sizeof(unsigned short));

    split_x_kernel<<<BATCH * DIM / 256, 256>>>(x, b_dec);
    split_w_kernel<<<dim3(TDICT / 32, DIM / 32), 256>>>(W_enc);

    hgemm_kernel<<<dim3(BATCH / 128, TDICT / 128), 256>>>(b_enc);

    topk_approx_kernel<<<BATCH, 256, TDICT * sizeof(unsigned short)>>>();
    refine_kernel<<<BATCH, 256>>>(b_enc);

    decode_kernel<<<BATCH, 256>>>(W_dec, b_dec, out);
}